// round 2
// baseline (speedup 1.0000x reference)
#include <cuda_runtime.h>
#include <math.h>

// Fixed problem shapes
#define TT 32      // T
#define NN 8       // neighbors
#define DD 64      // embedding dim
#define NRR 32     // num relations
#define BMAX 512

// w1,w2,w3 folded vectors: [3][64]
__device__ __align__(16) float g_w[3 * DD];
// e_u / e_v accumulators: [side][B][D]
__device__ __align__(16) float g_e[2][BMAX * DD];

// ---------------------------------------------------------------------------
// Kernel 1: fold W_GAT @ a_GAT slices into three 64-vectors.
//   w_k[d] = sum_j W[d][j] * a[k*64 + j]
// ---------------------------------------------------------------------------
__global__ void ckgat_prep(const float* __restrict__ W, const float* __restrict__ a) {
    int d = threadIdx.x;  // 64 threads
    float s0 = 0.f, s1 = 0.f, s2 = 0.f;
    #pragma unroll 8
    for (int j = 0; j < DD; j++) {
        float w = W[d * DD + j];
        s0 += w * a[j];
        s1 += w * a[DD + j];
        s2 += w * a[2 * DD + j];
    }
    g_w[d] = s0;
    g_w[DD + d] = s1;
    g_w[2 * DD + d] = s2;
}

// ---------------------------------------------------------------------------
// Kernel 2: main GAT. One block per (side, b). 8 warps, each warp owns
// (layer, t) units u = warp, warp+8, ... Full sum (layers + base terms)
// written to g_e[side][b][:].
// ---------------------------------------------------------------------------
__global__ __launch_bounds__(256) void ckgat_main(
    const int* __restrict__ items,
    const int* __restrict__ user_h,  const int* __restrict__ user_t,
    const int* __restrict__ user_nh, const int* __restrict__ user_nr, const int* __restrict__ user_nt,
    const int* __restrict__ item_h,  const int* __restrict__ item_t,
    const int* __restrict__ item_nh, const int* __restrict__ item_nr, const int* __restrict__ item_nt,
    const float* __restrict__ E,     // entity_emb [NE,64]
    const float* __restrict__ R,     // relation_emb [32,64]
    const float* __restrict__ W,     // W_GAT [64,64]
    int B, int L)
{
    __shared__ float sW[DD * DD];     // 16 KB
    __shared__ float sR[NRR * DD];    // 8 KB
    __shared__ float sX[8][DD];       // per-warp x vector, 2 KB
    __shared__ float2 sAcc[8][32];    // block reduction, 2 KB

    const int tid  = threadIdx.x;
    const int lane = tid & 31;
    const int warp = tid >> 5;
    const int side = blockIdx.x & 1;
    const int b    = blockIdx.x >> 1;

    // Stage W and relation table
    for (int i = tid; i < DD * DD; i += 256) sW[i] = W[i];
    for (int i = tid; i < NRR * DD; i += 256) sR[i] = R[i];
    __syncthreads();

    // Per-lane slices of folded vectors: dims {2*lane, 2*lane+1}
    const float2 w1 = *(const float2*)&g_w[2 * lane];
    const float2 w2 = *(const float2*)&g_w[DD + 2 * lane];
    const float2 w3 = *(const float2*)&g_w[2 * DD + 2 * lane];

    const int* nhp = side ? item_nh : user_nh;
    const int* nrp = side ? item_nr : user_nr;
    const int* ntp = side ? item_nt : user_nt;
    const int* tp  = side ? item_t  : user_t;

    float2 acc = make_float2(0.f, 0.f);

    const int nUnits = L * TT;
    for (int u = warp; u < nUnits; u += 8) {
        const int l = u >> 5;       // layer (T=32)
        const int t = u & 31;
        const long b3 = ((long)l * B + b) * TT + t;
        const long b4 = b3 * NN;

        float2 eh[NN];
        float  pp[NN];
        #pragma unroll
        for (int n = 0; n < NN; n++) {
            int hi = nhp[b4 + n];
            int ti = ntp[b4 + n];
            int ri = nrp[b4 + n];
            float2 e  = *(const float2*)&E[(long)hi * DD + 2 * lane];
            float2 et = *(const float2*)&E[(long)ti * DD + 2 * lane];
            float2 er = *(const float2*)&sR[ri * DD + 2 * lane];
            eh[n] = e;
            pp[n] = e.x * w1.x + e.y * w1.y
                  + er.x * w2.x + er.y * w2.y
                  + et.x * w3.x + et.y * w3.y;
        }
        // full-warp butterfly reduce each of the 8 logits
        #pragma unroll
        for (int n = 0; n < NN; n++) {
            #pragma unroll
            for (int off = 16; off; off >>= 1)
                pp[n] += __shfl_xor_sync(0xffffffffu, pp[n], off);
        }
        // leaky relu + softmax over 8 neighbors (redundant per lane, cheap)
        float m = -1e30f;
        #pragma unroll
        for (int n = 0; n < NN; n++) {
            pp[n] = pp[n] > 0.f ? pp[n] : 0.2f * pp[n];
            m = fmaxf(m, pp[n]);
        }
        float s = 0.f;
        #pragma unroll
        for (int n = 0; n < NN; n++) { pp[n] = __expf(pp[n] - m); s += pp[n]; }
        const float inv = 1.f / s;

        // x = sum_n att[n]*eh[n] + E[t_idx]
        const int tix = tp[b3];
        float2 x = *(const float2*)&E[(long)tix * DD + 2 * lane];
        #pragma unroll
        for (int n = 0; n < NN; n++) {
            const float a_ = pp[n] * inv;
            x.x += a_ * eh[n].x;
            x.y += a_ * eh[n].y;
        }

        // y = elu(x @ W): lane owns outputs j = {2*lane, 2*lane+1}
        sX[warp][2 * lane]     = x.x;
        sX[warp][2 * lane + 1] = x.y;
        __syncwarp();
        float y0 = 0.f, y1 = 0.f;
        #pragma unroll
        for (int d = 0; d < DD; d++) {
            const float xv = sX[warp][d];
            const float2 w = *(const float2*)&sW[d * DD + 2 * lane];
            y0 += xv * w.x;
            y1 += xv * w.y;
        }
        __syncwarp();  // protect sX before next unit overwrites
        y0 = y0 > 0.f ? y0 : (__expf(y0) - 1.f);
        y1 = y1 > 0.f ? y1 : (__expf(y1) - 1.f);
        acc.x += y0;
        acc.y += y1;
    }

    // base term: mean over T of entity_emb[h0[b][t]]  (layer-0 h indices)
    {
        const int* hp = side ? item_h : user_h;
        const float sc = 1.f / 32.f;
        for (int t = warp * 4; t < warp * 4 + 4; t++) {
            int hi = hp[(long)b * TT + t];
            float2 e = *(const float2*)&E[(long)hi * DD + 2 * lane];
            acc.x += e.x * sc;
            acc.y += e.y * sc;
        }
    }
    // item side extra: entity_emb[items[b]]
    if (side == 1 && warp == 0) {
        int ii = items[b];
        float2 e = *(const float2*)&E[(long)ii * DD + 2 * lane];
        acc.x += e.x;
        acc.y += e.y;
    }

    sAcc[warp][lane] = acc;
    __syncthreads();
    if (warp == 0) {
        float2 r = sAcc[0][lane];
        #pragma unroll
        for (int w = 1; w < 8; w++) {
            r.x += sAcc[w][lane].x;
            r.y += sAcc[w][lane].y;
        }
        *(float2*)&g_e[side][(long)b * DD + 2 * lane] = r;
    }
}

// ---------------------------------------------------------------------------
// Kernel 3: out[b] = sigmoid(dot(e_u[b], e_v[b]))
// ---------------------------------------------------------------------------
__global__ void ckgat_final(float* __restrict__ out, int B) {
    const int lane = threadIdx.x & 31;
    const int b = blockIdx.x * 8 + (threadIdx.x >> 5);
    if (b >= B) return;
    float2 u = *(const float2*)&g_e[0][(long)b * DD + 2 * lane];
    float2 v = *(const float2*)&g_e[1][(long)b * DD + 2 * lane];
    float d = u.x * v.x + u.y * v.y;
    #pragma unroll
    for (int off = 16; off; off >>= 1)
        d += __shfl_xor_sync(0xffffffffu, d, off);
    if (lane == 0) out[b] = 1.f / (1.f + __expf(-d));
}

// ---------------------------------------------------------------------------
// launch
// inputs (metadata order):
//  0 items, 1 user_h, 2 user_r, 3 user_t, 4 user_nh, 5 user_nr, 6 user_nt,
//  7 item_h, 8 item_r, 9 item_t, 10 item_nh, 11 item_nr, 12 item_nt,
//  13 entity_emb, 14 relation_emb, 15 W_GAT, 16 a_GAT
// ---------------------------------------------------------------------------
extern "C" void kernel_launch(void* const* d_in, const int* in_sizes, int n_in,
                              void* d_out, int out_size) {
    const int*   items   = (const int*)d_in[0];
    const int*   user_h  = (const int*)d_in[1];
    const int*   user_t  = (const int*)d_in[3];
    const int*   user_nh = (const int*)d_in[4];
    const int*   user_nr = (const int*)d_in[5];
    const int*   user_nt = (const int*)d_in[6];
    const int*   item_h  = (const int*)d_in[7];
    const int*   item_t  = (const int*)d_in[9];
    const int*   item_nh = (const int*)d_in[10];
    const int*   item_nr = (const int*)d_in[11];
    const int*   item_nt = (const int*)d_in[12];
    const float* E       = (const float*)d_in[13];
    const float* R       = (const float*)d_in[14];
    const float* W       = (const float*)d_in[15];
    const float* a       = (const float*)d_in[16];
    float* out = (float*)d_out;

    const int B = in_sizes[0];
    int L = in_sizes[1] / (B * TT);
    if (L < 1) L = 1;

    ckgat_prep<<<1, 64>>>(W, a);
    ckgat_main<<<2 * B, 256>>>(items, user_h, user_t, user_nh, user_nr, user_nt,
                               item_h, item_t, item_nh, item_nr, item_nt,
                               E, R, W, B, L);
    ckgat_final<<<(B + 7) / 8, 256>>>(out, B);
}

// round 4
// speedup vs baseline: 1.1579x; 1.1579x over previous
#include <cuda_runtime.h>
#include <math.h>

// Fixed problem shapes
#define TT 32      // T
#define NN 8       // neighbors
#define DD 64      // embedding dim
#define NRR 32     // num relations

// ---------------------------------------------------------------------------
// Single fused kernel. Block = batch index b (512 blocks, 256 threads).
//   warps 0-3: user side   (64 units = L*T, 16 per warp)
//   warps 4-7: item side
// Phases per warp, per batch of 8 units:
//   A) gather + attention -> x vector into sX
//   B) batched matvec: read each W row once, FMA against 8 x broadcasts
// Then block reduce per side, dot(e_u,e_v), sigmoid -> out[b].
// ---------------------------------------------------------------------------
__global__ __launch_bounds__(256) void ckgat_fused(
    const int* __restrict__ items,
    const int* __restrict__ user_h,  const int* __restrict__ user_t,
    const int* __restrict__ user_nh, const int* __restrict__ user_nr, const int* __restrict__ user_nt,
    const int* __restrict__ item_h,  const int* __restrict__ item_t,
    const int* __restrict__ item_nh, const int* __restrict__ item_nr, const int* __restrict__ item_nt,
    const float* __restrict__ E,     // entity_emb [NE,64]
    const float* __restrict__ R,     // relation_emb [32,64]
    const float* __restrict__ W,     // W_GAT [64,64]
    const float* __restrict__ aG,    // a_GAT [3*64]
    float* __restrict__ out,
    int B, int L)
{
    __shared__ float  sW[DD * DD];       // 16 KB
    __shared__ float  sR[NRR * DD];      // 8 KB
    __shared__ float  sw[3 * DD];        // folded W@a slices, 768 B
    __shared__ float  sX[8][8][DD];      // warp, slot, dim: 16 KB
    __shared__ float2 sAcc[8][32];       // 2 KB

    const int tid  = threadIdx.x;
    const int lane = tid & 31;
    const int warp = tid >> 5;
    const int side = warp >> 2;          // 0 = user, 1 = item
    const int wu   = warp & 3;           // warp-in-side
    const int b    = blockIdx.x;

    // Stage W and relation table; fold w_k[d] = sum_j W[d][j]*a[k*64+j]
    for (int i = tid; i < DD * DD; i += 256) sW[i] = W[i];
    for (int i = tid; i < NRR * DD; i += 256) sR[i] = R[i];
    if (tid < DD) {
        float s0 = 0.f, s1 = 0.f, s2 = 0.f;
        #pragma unroll 8
        for (int j = 0; j < DD; j++) {
            float w = W[tid * DD + j];
            s0 += w * aG[j];
            s1 += w * aG[DD + j];
            s2 += w * aG[2 * DD + j];
        }
        sw[tid] = s0; sw[DD + tid] = s1; sw[2 * DD + tid] = s2;
    }
    __syncthreads();

    // Per-lane slices of folded vectors: dims {2*lane, 2*lane+1}
    const float2 w1 = *(const float2*)&sw[2 * lane];
    const float2 w2 = *(const float2*)&sw[DD + 2 * lane];
    const float2 w3 = *(const float2*)&sw[2 * DD + 2 * lane];

    const int* nhp = side ? item_nh : user_nh;
    const int* nrp = side ? item_nr : user_nr;
    const int* ntp = side ? item_nt : user_nt;
    const int* tp  = side ? item_t  : user_t;

    float2 acc = make_float2(0.f, 0.f);

    const int nUnits  = L * TT;              // 64 for L=2
    const int perWarp = nUnits / 4;          // 16
    const int nBatch  = (perWarp + 7) / 8;   // 2

    for (int jb = 0; jb < nBatch; jb++) {
        const int nIn = (perWarp - jb * 8) < 8 ? (perWarp - jb * 8) : 8;

        // -------- Phase A: attention for nIn units; x -> sX --------
        for (int i = 0; i < nIn; i++) {
            const int u = wu + 4 * (jb * 8 + i);   // unit id, unique over warps-in-side
            const int l = u >> 5;                  // layer (T=32)
            const int t = u & 31;
            const long b3 = ((long)l * B + b) * TT + t;
            const long b4 = b3 * NN;

            // Front-batch all 24 neighbor indices (contiguous: N=8 innermost)
            const int4 nh0 = *(const int4*)&nhp[b4];
            const int4 nh1 = *(const int4*)&nhp[b4 + 4];
            const int4 nt0 = *(const int4*)&ntp[b4];
            const int4 nt1 = *(const int4*)&ntp[b4 + 4];
            const int4 nr0 = *(const int4*)&nrp[b4];
            const int4 nr1 = *(const int4*)&nrp[b4 + 4];
            int hidx[NN] = {nh0.x, nh0.y, nh0.z, nh0.w, nh1.x, nh1.y, nh1.z, nh1.w};
            int tidx[NN] = {nt0.x, nt0.y, nt0.z, nt0.w, nt1.x, nt1.y, nt1.z, nt1.w};
            int ridx[NN] = {nr0.x, nr0.y, nr0.z, nr0.w, nr1.x, nr1.y, nr1.z, nr1.w};

            float2 eh[NN];
            float  pp[NN];
            #pragma unroll
            for (int n = 0; n < NN; n++) {
                float2 e  = *(const float2*)&E[(long)hidx[n] * DD + 2 * lane];
                float2 et = *(const float2*)&E[(long)tidx[n] * DD + 2 * lane];
                float2 er = *(const float2*)&sR[ridx[n] * DD + 2 * lane];
                eh[n] = e;
                pp[n] = e.x * w1.x + e.y * w1.y
                      + er.x * w2.x + er.y * w2.y
                      + et.x * w3.x + et.y * w3.y;
            }
            #pragma unroll
            for (int n = 0; n < NN; n++) {
                #pragma unroll
                for (int off = 16; off; off >>= 1)
                    pp[n] += __shfl_xor_sync(0xffffffffu, pp[n], off);
            }
            // leaky relu + softmax over 8 neighbors (redundant per lane)
            float m = -1e30f;
            #pragma unroll
            for (int n = 0; n < NN; n++) {
                pp[n] = pp[n] > 0.f ? pp[n] : 0.2f * pp[n];
                m = fmaxf(m, pp[n]);
            }
            float s = 0.f;
            #pragma unroll
            for (int n = 0; n < NN; n++) { pp[n] = __expf(pp[n] - m); s += pp[n]; }
            const float inv = 1.f / s;

            const int tix = tp[b3];
            float2 x = *(const float2*)&E[(long)tix * DD + 2 * lane];
            #pragma unroll
            for (int n = 0; n < NN; n++) {
                const float a_ = pp[n] * inv;
                x.x += a_ * eh[n].x;
                x.y += a_ * eh[n].y;
            }
            *(float2*)&sX[warp][i][2 * lane] = x;
        }
        __syncwarp();

        // -------- Phase B: batched matvec y_i = elu(x_i @ W) --------
        float2 y[8];
        #pragma unroll
        for (int i = 0; i < 8; i++) y[i] = make_float2(0.f, 0.f);
        for (int d = 0; d < DD; d++) {
            const float2 w = *(const float2*)&sW[d * DD + 2 * lane];
            #pragma unroll
            for (int i = 0; i < 8; i++) {
                const float xv = sX[warp][i][d];   // broadcast
                y[i].x += xv * w.x;
                y[i].y += xv * w.y;
            }
        }
        for (int i = 0; i < nIn; i++) {
            float y0 = y[i].x, y1 = y[i].y;
            y0 = y0 > 0.f ? y0 : (__expf(y0) - 1.f);
            y1 = y1 > 0.f ? y1 : (__expf(y1) - 1.f);
            acc.x += y0;
            acc.y += y1;
        }
        __syncwarp();
    }

    // Base term: mean over T of E[h0[b][t]]; each warp-in-side takes 8 t's
    {
        const int* hp = side ? item_h : user_h;
        const float sc = 1.f / (float)TT;
        for (int t = wu * 8; t < wu * 8 + 8; t++) {
            int hi = hp[(long)b * TT + t];
            float2 e = *(const float2*)&E[(long)hi * DD + 2 * lane];
            acc.x += e.x * sc;
            acc.y += e.y * sc;
        }
    }
    // Item-side extra: E[items[b]]
    if (side == 1 && wu == 0) {
        int ii = items[b];
        float2 e = *(const float2*)&E[(long)ii * DD + 2 * lane];
        acc.x += e.x;
        acc.y += e.y;
    }

    sAcc[warp][lane] = acc;
    __syncthreads();

    // Warp 0: reduce both sides, dot, sigmoid, write
    if (warp == 0) {
        float2 u = sAcc[0][lane];
        float2 v = sAcc[4][lane];
        #pragma unroll
        for (int w = 1; w < 4; w++) {
            u.x += sAcc[w][lane].x;     u.y += sAcc[w][lane].y;
            v.x += sAcc[4 + w][lane].x; v.y += sAcc[4 + w][lane].y;
        }
        float d = u.x * v.x + u.y * v.y;
        #pragma unroll
        for (int off = 16; off; off >>= 1)
            d += __shfl_xor_sync(0xffffffffu, d, off);
        if (lane == 0) out[b] = 1.f / (1.f + __expf(-d));
    }
}

// ---------------------------------------------------------------------------
// launch. Inputs (metadata order):
//  0 items, 1 user_h, 2 user_r, 3 user_t, 4 user_nh, 5 user_nr, 6 user_nt,
//  7 item_h, 8 item_r, 9 item_t, 10 item_nh, 11 item_nr, 12 item_nt,
//  13 entity_emb, 14 relation_emb, 15 W_GAT, 16 a_GAT
// ---------------------------------------------------------------------------
extern "C" void kernel_launch(void* const* d_in, const int* in_sizes, int n_in,
                              void* d_out, int out_size) {
    const int*   items   = (const int*)d_in[0];
    const int*   user_h  = (const int*)d_in[1];
    const int*   user_t  = (const int*)d_in[3];
    const int*   user_nh = (const int*)d_in[4];
    const int*   user_nr = (const int*)d_in[5];
    const int*   user_nt = (const int*)d_in[6];
    const int*   item_h  = (const int*)d_in[7];
    const int*   item_t  = (const int*)d_in[9];
    const int*   item_nh = (const int*)d_in[10];
    const int*   item_nr = (const int*)d_in[11];
    const int*   item_nt = (const int*)d_in[12];
    const float* E       = (const float*)d_in[13];
    const float* R       = (const float*)d_in[14];
    const float* W       = (const float*)d_in[15];
    const float* a       = (const float*)d_in[16];
    float* out = (float*)d_out;

    const int B = in_sizes[0];
    int L = in_sizes[1] / (B * TT);
    if (L < 1) L = 1;

    ckgat_fused<<<B, 256>>>(items, user_h, user_t, user_nh, user_nr, user_nt,
                            item_h, item_t, item_nh, item_nr, item_nt,
                            E, R, W, a, out, B, L);
}